// round 17
// baseline (speedup 1.0000x reference)
#include <cuda_runtime.h>
#include <cuda_fp16.h>
#include <math.h>
#include <stdint.h>

// ---------------- problem constants ----------------
constexpr int HD   = 1024;
constexpr int ID   = 512;
constexpr int NEXP = 16;
constexpr int TOPK = 4;
constexpr int NT   = 2048;
constexpr int NE   = 17;          // 16 routed + shared pseudo-expert

// ---------------- device scratch ----------------
__device__ int    g_cnt[NE];
__device__ int    g_tok[NE * NT];
__device__ float  g_rw [NE * NT];
__device__ int    g_pos[NT * TOPK];
__device__ __half g_xh[(size_t)NT * HD];
__device__ __half g_acth[(size_t)NE * NT * ID];   // gathered SwiGLU activations
__device__ __half g_dnh [(size_t)NE * NT * HD];   // per-(expert,slot) down outputs

// ---------------- helpers ----------------
__device__ __forceinline__ uint32_t smem_u32(const void* p) {
    uint32_t a;
    asm("{ .reg .u64 t; cvta.to.shared.u64 t, %1; cvt.u32.u64 %0, t; }" : "=r"(a) : "l"(p));
    return a;
}
__device__ __forceinline__ void cp16(uint32_t dst, const void* src) {
    asm volatile("cp.async.cg.shared.global [%0], [%1], 16;" :: "r"(dst), "l"(src));
}
#define CP_COMMIT() asm volatile("cp.async.commit_group;" ::: "memory")
#define CP_WAIT(n)  asm volatile("cp.async.wait_group %0;" :: "n"(n) : "memory")

#define LDSM4(r, a)                                                              \
    asm volatile("ldmatrix.sync.aligned.m8n8.x4.shared.b16 {%0,%1,%2,%3}, [%4];" \
        : "=r"((r)[0]), "=r"((r)[1]), "=r"((r)[2]), "=r"((r)[3]) : "r"(a))
#define LDSM4T(r, a)                                                             \
    asm volatile("ldmatrix.sync.aligned.m8n8.x4.trans.shared.b16 {%0,%1,%2,%3}, [%4];" \
        : "=r"((r)[0]), "=r"((r)[1]), "=r"((r)[2]), "=r"((r)[3]) : "r"(a))

// mma m16n8k16 f16 -> f32.  C: c0=(g,2tg) c1=(g,2tg+1) c2=(g+8,2tg) c3=(g+8,2tg+1)
__device__ __forceinline__ void mma16(float* c, const uint32_t* a, uint32_t b0, uint32_t b1) {
    asm volatile(
        "mma.sync.aligned.m16n8k16.row.col.f32.f16.f16.f32 "
        "{%0,%1,%2,%3}, {%4,%5,%6,%7}, {%8,%9}, {%0,%1,%2,%3};"
        : "+f"(c[0]), "+f"(c[1]), "+f"(c[2]), "+f"(c[3])
        : "r"(a[0]), "r"(a[1]), "r"(a[2]), "r"(a[3]), "r"(b0), "r"(b1));
}
// silu via single-MUFU tanh.approx: silu(g) = 0.5*g*(1 + tanh(g/2))
__device__ __forceinline__ float silu(float g) {
    float t;
    asm("tanh.approx.f32 %0, %1;" : "=f"(t) : "f"(0.5f * g));
    return 0.5f * g * (1.f + t);
}
__device__ __forceinline__ uint2 f4_to_h4(float4 v) {
    __half2 a = __floats2half2_rn(v.x, v.y);
    __half2 b = __floats2half2_rn(v.z, v.w);
    uint2 o;
    o.x = *(uint32_t*)&a; o.y = *(uint32_t*)&b;
    return o;
}

// ---------------- init: reset counters (tiny; must precede k_prep atomics) ----------------
__global__ void k_init() {
    if (threadIdx.x < NE) g_cnt[threadIdx.x] = (threadIdx.x == NEXP) ? NT : 0;
}

// ---------------- prep: one block per token ----------------
__global__ void __launch_bounds__(256)
k_prep(const float* __restrict__ x, const float* __restrict__ rw) {
    const int t   = blockIdx.x;
    const int tid = threadIdx.x;
    __shared__ float xs[HD];
    __shared__ float sl[NEXP];

    {
        float4 v = *(const float4*)(x + (size_t)t * HD + tid * 4);
        *(float4*)(xs + tid * 4) = v;
        __half2 h0 = __floats2half2_rn(v.x, v.y);
        __half2 h1 = __floats2half2_rn(v.z, v.w);
        uint2 o; o.x = *(uint32_t*)&h0; o.y = *(uint32_t*)&h1;
        *(uint2*)(g_xh + (size_t)t * HD + tid * 4) = o;
    }
    if (tid == 0) { g_tok[NEXP * NT + t] = t; g_rw[NEXP * NT + t] = 1.0f; }
    __syncthreads();

    const int w    = tid >> 5;
    const int lane = tid & 31;
    #pragma unroll
    for (int half = 0; half < 2; half++) {
        int e = w + half * 8;
        float acc = 0.f;
        for (int h = lane; h < HD; h += 32)
            acc += xs[h] * rw[h * NEXP + e];
        #pragma unroll
        for (int o = 16; o > 0; o >>= 1)
            acc += __shfl_down_sync(0xffffffffu, acc, o);
        if (lane == 0) sl[e] = acc;
    }
    __syncthreads();

    if (tid == 0) {
        float v[NEXP]; bool used[NEXP];
        #pragma unroll
        for (int e = 0; e < NEXP; e++) { v[e] = 1.f / (1.f + expf(-sl[e])); used[e] = false; }
        #pragma unroll
        for (int k = 0; k < TOPK; k++) {
            int be = -1; float bv = -1.f;
            #pragma unroll
            for (int e = 0; e < NEXP; e++)
                if (!used[e] && v[e] > bv) { bv = v[e]; be = e; }
            used[be] = true;
            int j = atomicAdd(&g_cnt[be], 1);
            g_tok[be * NT + j] = t;
            g_rw [be * NT + j] = bv;
            g_pos[t * TOPK + k] = be * NT + j;
        }
    }
}

// =======================================================================
// gate/up: BM=128, BN=64 (G and U), BK=32, 256 thr / 8 warps (4m x 2n).
// Epilogue staged through smem -> coalesced uint4 global stores.
// =======================================================================
constexpr int GU_ASTG = 128 * 40;
constexpr int GU_BSTG = 32 * 72;
constexpr int GU_SMEM = 1024 + (3 * GU_ASTG + 6 * GU_BSTG) * 2;   // 59392 B

__global__ void __launch_bounds__(256, 2)
k_gateup(const float* __restrict__ gate_w, const float* __restrict__ up_w,
         const float* __restrict__ sgate,  const float* __restrict__ sup) {
    const int e    = blockIdx.z;
    const int c    = g_cnt[e];
    const int row0 = blockIdx.x * 128;
    if (row0 >= c) return;
    const int n0   = blockIdx.y * 64;

    extern __shared__ char smc[];
    int*    toks = (int*)smc;
    float*  rws  = (float*)(smc + 512);
    __half* sA   = (__half*)(smc + 1024);
    __half* sG   = sA + 3 * GU_ASTG;
    __half* sU   = sG + 3 * GU_BSTG;
    __half* sOut = (__half*)(smc + 1024);             // 128x64 halves, reuses A/B rings
    const int tid = threadIdx.x;

    const float* Wg = (e == NEXP) ? sgate : gate_w + (size_t)e * HD * ID;
    const float* Wu = (e == NEXP) ? sup   : up_w   + (size_t)e * HD * ID;

    if (tid < 128) {
        int r = row0 + tid;
        if (r < c) { toks[tid] = g_tok[e * NT + r]; rws[tid] = g_rw[e * NT + r]; }
        else       { toks[tid] = 0;                 rws[tid] = 0.f; }
    }
    __syncthreads();

    const uint32_t abA = smem_u32(sA);

    auto ldA = [&](int buf, int kk) {
        uint32_t dA = abA + buf * GU_ASTG * 2;
        #pragma unroll
        for (int i = 0; i < 2; i++) {
            int lin = tid + i * 256;
            int r = lin >> 2, q = lin & 3;
            cp16(dA + (r * 40 + q * 8) * 2, g_xh + (size_t)toks[r] * HD + kk + q * 8);
        }
    };

    float4 wg4[2], wu4[2];
    auto ldgB = [&](int kk) {
        #pragma unroll
        for (int i = 0; i < 2; i++) {
            int lin = tid + i * 256;
            int k = lin >> 4, n4 = lin & 15;
            wg4[i] = *(const float4*)(Wg + (size_t)(kk + k) * ID + n0 + n4 * 4);
            wu4[i] = *(const float4*)(Wu + (size_t)(kk + k) * ID + n0 + n4 * 4);
        }
    };
    auto stsB = [&](int buf) {
        #pragma unroll
        for (int i = 0; i < 2; i++) {
            int lin = tid + i * 256;
            int k = lin >> 4, n4 = lin & 15;
            *(uint2*)(sG + buf * GU_BSTG + k * 72 + n4 * 4) = f4_to_h4(wg4[i]);
            *(uint2*)(sU + buf * GU_BSTG + k * 72 + n4 * 4) = f4_to_h4(wu4[i]);
        }
    };

    const int wid = tid >> 5, lane = tid & 31;
    const int gid = lane >> 2, tg = lane & 3;
    const int wm = wid & 3, wn = wid >> 2;
    const int l15 = lane & 15, l16 = lane >> 4;
    const uint32_t abG = smem_u32(sG), abU = smem_u32(sU);

    float accG[2][4][4] = {}, accU[2][4][4] = {};

    ldA(0, 0);  CP_COMMIT();
    ldA(1, 32); CP_COMMIT();
    ldgB(0);    stsB(0);
    ldgB(32);

    const int S = HD / 32;
    for (int s = 0; s < S; s++) {
        if (s + 1 < S) { CP_WAIT(1); } else { CP_WAIT(0); }
        __syncthreads();
        if (s + 2 < S) ldA((s + 2) % 3, (s + 2) * 32);
        CP_COMMIT();

        uint32_t bA = abA + (s % 3) * GU_ASTG * 2;
        uint32_t bG = abG + (s % 3) * GU_BSTG * 2;
        uint32_t bU = abU + (s % 3) * GU_BSTG * 2;

        #pragma unroll
        for (int kq = 0; kq < 2; kq++) {
            uint32_t a[2][4], bg[2][4], bu[2][4];
            #pragma unroll
            for (int mf = 0; mf < 2; mf++)
                LDSM4(a[mf], bA + ((wm * 32 + mf * 16 + l15) * 40 + kq * 16 + l16 * 8) * 2);
            #pragma unroll
            for (int h = 0; h < 2; h++) {
                LDSM4T(bg[h], bG + ((kq * 16 + l15) * 72 + wn * 32 + h * 16 + l16 * 8) * 2);
                LDSM4T(bu[h], bU + ((kq * 16 + l15) * 72 + wn * 32 + h * 16 + l16 * 8) * 2);
            }
            #pragma unroll
            for (int mf = 0; mf < 2; mf++)
                #pragma unroll
                for (int h = 0; h < 2; h++) {
                    mma16(accG[mf][2 * h + 0], a[mf], bg[h][0], bg[h][1]);
                    mma16(accG[mf][2 * h + 1], a[mf], bg[h][2], bg[h][3]);
                    mma16(accU[mf][2 * h + 0], a[mf], bu[h][0], bu[h][1]);
                    mma16(accU[mf][2 * h + 1], a[mf], bu[h][2], bu[h][3]);
                }
        }

        if (s + 1 < S) stsB((s + 1) % 3);
        if (s + 2 < S) ldgB((s + 2) * 32);
    }

    // epilogue: silu(r*g)*(r*u) -> smem tile (128x64h) -> coalesced stores
    __syncthreads();                                  // all ldmatrix done; safe to reuse smem
    #pragma unroll
    for (int mf = 0; mf < 2; mf++) {
        int rl = wm * 32 + mf * 16 + gid;
        float rr0 = rws[rl], rr1 = rws[rl + 8];
        __half* q0 = sOut + rl * 64       + wn * 32 + 2 * tg;
        __half* q1 = sOut + (rl + 8) * 64 + wn * 32 + 2 * tg;
        #pragma unroll
        for (int nf = 0; nf < 4; nf++) {
            float g0 = rr0 * accG[mf][nf][0], u0 = rr0 * accU[mf][nf][0];
            float g1 = rr0 * accG[mf][nf][1], u1 = rr0 * accU[mf][nf][1];
            float g2 = rr1 * accG[mf][nf][2], u2 = rr1 * accU[mf][nf][2];
            float g3 = rr1 * accG[mf][nf][3], u3 = rr1 * accU[mf][nf][3];
            *(__half2*)(q0 + nf * 8) = __floats2half2_rn(silu(g0) * u0, silu(g1) * u1);
            *(__half2*)(q1 + nf * 8) = __floats2half2_rn(silu(g2) * u2, silu(g3) * u3);
        }
    }
    __syncthreads();
    #pragma unroll
    for (int it = 0; it < 4; it++) {                  // 128 rows x 8 uint4
        int idx = tid + it * 256;
        int r = idx >> 3, q = idx & 7;
        *(uint4*)(g_acth + ((size_t)e * NT + row0 + r) * ID + n0 + q * 8) =
            *(uint4*)(sOut + r * 64 + q * 8);
    }
}

// =======================================================================
// down: BM=128, BN=128, BK=32, 256 thr / 8 warps (4m x 2n), warp tile 32x64.
// Epilogue staged through smem -> coalesced uint4 global stores.
// =======================================================================
constexpr int DN_ASTG = 128 * 40;
constexpr int DN_BSTG = 32 * 136;
constexpr int DN_SMEM = (3 * DN_ASTG + 3 * DN_BSTG) * 2;   // 56832 B (>= 32KB out tile)

__global__ void __launch_bounds__(256, 2)
k_down(const float* __restrict__ down_w, const float* __restrict__ sdown) {
    const int e    = blockIdx.z;
    const int c    = g_cnt[e];
    const int row0 = blockIdx.x * 128;
    if (row0 >= c) return;
    const int n0   = blockIdx.y * 128;

    extern __shared__ char smc[];
    __half* sA = (__half*)smc;
    __half* sB = sA + 3 * DN_ASTG;
    __half* sOut = (__half*)smc;                      // 128x128 halves = 32KB, reuses rings
    const int tid = threadIdx.x;

    const float* Wd = (e == NEXP) ? sdown : down_w + (size_t)e * ID * HD;
    const __half* Ab = g_acth + ((size_t)e * NT + row0) * ID;

    const uint32_t abA = smem_u32(sA), abB = smem_u32(sB);

    auto ldA = [&](int buf, int kk) {
        uint32_t dA = abA + buf * DN_ASTG * 2;
        #pragma unroll
        for (int i = 0; i < 2; i++) {
            int lin = tid + i * 256;
            int r = lin >> 2, q = lin & 3;
            cp16(dA + (r * 40 + q * 8) * 2, Ab + (size_t)r * ID + kk + q * 8);
        }
    };

    float4 wd4[4];
    auto ldgB = [&](int kk) {
        #pragma unroll
        for (int i = 0; i < 4; i++) {
            int lin = tid + i * 256;
            int k = lin >> 5, n4 = lin & 31;
            wd4[i] = *(const float4*)(Wd + (size_t)(kk + k) * HD + n0 + n4 * 4);
        }
    };
    auto stsB = [&](int buf) {
        #pragma unroll
        for (int i = 0; i < 4; i++) {
            int lin = tid + i * 256;
            int k = lin >> 5, n4 = lin & 31;
            *(uint2*)(sB + buf * DN_BSTG + k * 136 + n4 * 4) = f4_to_h4(wd4[i]);
        }
    };

    const int wid = tid >> 5, lane = tid & 31;
    const int gid = lane >> 2, tg = lane & 3;
    const int wm = wid & 3, wn = wid >> 2;
    const int l15 = lane & 15, l16 = lane >> 4;

    float acc[2][8][4] = {};

    ldA(0, 0);  CP_COMMIT();
    ldA(1, 32); CP_COMMIT();
    ldgB(0);    stsB(0);
    ldgB(32);

    const int S = ID / 32;
    for (int s = 0; s < S; s++) {
        if (s + 1 < S) { CP_WAIT(1); } else { CP_WAIT(0); }
        __syncthreads();
        if (s + 2 < S) ldA((s + 2) % 3, (s + 2) * 32);
        CP_COMMIT();

        uint32_t bA = abA + (s % 3) * DN_ASTG * 2;
        uint32_t bB = abB + (s % 3) * DN_BSTG * 2;

        #pragma unroll
        for (int kq = 0; kq < 2; kq++) {
            uint32_t a[2][4], b[4][4];
            #pragma unroll
            for (int mf = 0; mf < 2; mf++)
                LDSM4(a[mf], bA + ((wm * 32 + mf * 16 + l15) * 40 + kq * 16 + l16 * 8) * 2);
            #pragma unroll
            for (int h = 0; h < 4; h++)
                LDSM4T(b[h], bB + ((kq * 16 + l15) * 136 + wn * 64 + h * 16 + l16 * 8) * 2);
            #pragma unroll
            for (int mf = 0; mf < 2; mf++)
                #pragma unroll
                for (int h = 0; h < 4; h++) {
                    mma16(acc[mf][2 * h + 0], a[mf], b[h][0], b[h][1]);
                    mma16(acc[mf][2 * h + 1], a[mf], b[h][2], b[h][3]);
                }
        }

        if (s + 1 < S) stsB((s + 1) % 3);
        if (s + 2 < S) ldgB((s + 2) * 32);
    }

    // epilogue: smem tile (128x128h) -> coalesced stores
    __syncthreads();
    #pragma unroll
    for (int mf = 0; mf < 2; mf++) {
        int rl = wm * 32 + mf * 16 + gid;
        __half* q0 = sOut + rl * 128       + wn * 64 + 2 * tg;
        __half* q1 = sOut + (rl + 8) * 128 + wn * 64 + 2 * tg;
        #pragma unroll
        for (int nf = 0; nf < 8; nf++) {
            *(__half2*)(q0 + nf * 8) = __floats2half2_rn(acc[mf][nf][0], acc[mf][nf][1]);
            *(__half2*)(q1 + nf * 8) = __floats2half2_rn(acc[mf][nf][2], acc[mf][nf][3]);
        }
    }
    __syncthreads();
    #pragma unroll
    for (int it = 0; it < 8; it++) {                  // 128 rows x 16 uint4
        int idx = tid + it * 256;
        int r = idx >> 4, q = idx & 15;
        *(uint4*)(g_dnh + ((size_t)e * NT + row0 + r) * HD + n0 + q * 8) =
            *(uint4*)(sOut + r * 128 + q * 8);
    }
}

// ---------------- combine: out[t] = shared row + 4 routed rows (fp32) ----------------
__global__ void k_combine(float* __restrict__ out) {
    int t  = blockIdx.x;
    int c0 = threadIdx.x * 8;
    float acc[8];
    {
        const uint4 v = *(const uint4*)(g_dnh + ((size_t)NEXP * NT + t) * HD + c0);
        const __half2* h = (const __half2*)&v;
        #pragma unroll
        for (int j = 0; j < 4; j++) {
            float2 f = __half22float2(h[j]);
            acc[2 * j] = f.x; acc[2 * j + 1] = f.y;
        }
    }
    #pragma unroll
    for (int k = 0; k < TOPK; k++) {
        const uint4 v = *(const uint4*)(g_dnh + (size_t)g_pos[t * TOPK + k] * HD + c0);
        const __half2* h = (const __half2*)&v;
        #pragma unroll
        for (int j = 0; j < 4; j++) {
            float2 f = __half22float2(h[j]);
            acc[2 * j] += f.x; acc[2 * j + 1] += f.y;
        }
    }
    float* op = out + (size_t)t * HD + c0;
    *(float4*)op       = make_float4(acc[0], acc[1], acc[2], acc[3]);
    *(float4*)(op + 4) = make_float4(acc[4], acc[5], acc[6], acc[7]);
}

// ---------------- launch ----------------
extern "C" void kernel_launch(void* const* d_in, const int* in_sizes, int n_in,
                              void* d_out, int out_size) {
    (void)in_sizes; (void)n_in; (void)out_size;
    const float* x     = (const float*)d_in[0];
    const float* rw    = (const float*)d_in[1];
    const float* gate  = (const float*)d_in[2];
    const float* up    = (const float*)d_in[3];
    const float* down  = (const float*)d_in[4];
    const float* sgate = (const float*)d_in[5];
    const float* sup   = (const float*)d_in[6];
    const float* sdown = (const float*)d_in[7];
    float* out = (float*)d_out;

    cudaFuncSetAttribute(k_gateup, cudaFuncAttributeMaxDynamicSharedMemorySize, GU_SMEM);
    cudaFuncSetAttribute(k_down,   cudaFuncAttributeMaxDynamicSharedMemorySize, DN_SMEM);

    k_init<<<1, 32>>>();
    k_prep<<<NT, 256>>>(x, rw);
    k_gateup<<<dim3(NT / 128, ID / 64, NE), 256, GU_SMEM>>>(gate, up, sgate, sup);
    k_down  <<<dim3(NT / 128, HD / 128, NE), 256, DN_SMEM>>>(down, sdown);
    k_combine<<<NT, 128>>>(out);
}